// round 1
// baseline (speedup 1.0000x reference)
#include <cuda_runtime.h>

// Problem constants
#define Bn 8
#define Cc 512
#define Hh 14
#define Ww 14
#define HS 1024
#define Sp 196      // H*W
#define KC 144      // 12*12 interior centers
#define On 9        // 3x3 offsets

// Scratch (allocation-free rule: __device__ globals)
__device__ float g_P1[Bn * HS * Sp];     // w1-projection at all spatial positions (+b1)
__device__ float g_P2[Bn * HS * Sp];     // w2-projection at all spatial positions (+b2)
__device__ float g_ssq[Bn * On * HS];    // per (b,o,i) row sum of squares

// ---------------------------------------------------------------------------
// proj: out[b][h][s] = sum_c w[h][c] * x[b][c][s] + bias[h]
// CTA tile: 64 h x 32 s, 256 threads, each thread 4x2 micro-tile, K-chunks of 32.
// ---------------------------------------------------------------------------
__global__ __launch_bounds__(256) void proj_kernel(const float* __restrict__ x,
                                                   const float* __restrict__ w,
                                                   const float* __restrict__ bias,
                                                   int which)
{
    __shared__ __align__(16) float Wst[32 * 68];  // [c][h] transposed, 64 h + 4 pad
    __shared__ __align__(16) float Xs[32 * 33];   // [c][s], 32 s + 1 pad

    float* outP = which ? g_P2 : g_P1;
    const int tid = threadIdx.x;
    const int tx = tid & 15;
    const int ty = tid >> 4;
    const int sbase = blockIdx.x * 32;
    const int hbase = blockIdx.y * 64;
    const int b = blockIdx.z;

    float acc[4][2] = {};
    for (int cb = 0; cb < Cc; cb += 32) {
        // Load W tile (64h x 32c) transposed -> Wst[c][h]
        #pragma unroll
        for (int r = 0; r < 8; ++r) {
            int l = tid + r * 256;
            int h = l >> 5, c = l & 31;
            Wst[c * 68 + h] = w[(hbase + h) * Cc + cb + c];
        }
        // Load X tile (32c x 32s) -> Xs[c][s]
        #pragma unroll
        for (int r = 0; r < 4; ++r) {
            int l = tid + r * 256;
            int c = l >> 5, s = l & 31;
            int sg = sbase + s;
            Xs[c * 33 + s] = (sg < Sp) ? x[(b * Cc + cb + c) * Sp + sg] : 0.f;
        }
        __syncthreads();
        #pragma unroll 8
        for (int c = 0; c < 32; ++c) {
            float4 a = *(const float4*)(Wst + c * 68 + ty * 4);
            float b0 = Xs[c * 33 + tx * 2];
            float b1 = Xs[c * 33 + tx * 2 + 1];
            acc[0][0] += a.x * b0; acc[0][1] += a.x * b1;
            acc[1][0] += a.y * b0; acc[1][1] += a.y * b1;
            acc[2][0] += a.z * b0; acc[2][1] += a.z * b1;
            acc[3][0] += a.w * b0; acc[3][1] += a.w * b1;
        }
        __syncthreads();
    }
    #pragma unroll
    for (int u = 0; u < 4; ++u) {
        int h = hbase + ty * 4 + u;
        float bb = bias[h];
        #pragma unroll
        for (int v = 0; v < 2; ++v) {
            int s = sbase + tx * 2 + v;
            if (s < Sp) outP[(b * HS + h) * Sp + s] = acc[u][v] + bb;
        }
    }
}

// ---------------------------------------------------------------------------
// big: for each (b,o):  cofe[i][j] = sum_k P1[b,i,sc(k)] * P2[b,j,sc(k)+delta_o]
// CTA = (i_tile of 64, o, b). Loops all j in chunks of 64 so per-row sumsq is
// fully CTA-local (no atomics). Writes UNNORMALIZED cofe to out; norm pass rescales.
// 256 threads, 4x4 micro-tile, float4 smem reads.
// ---------------------------------------------------------------------------
#define TI 64
#define TJ 64
#define LDA 68
#define SMEM_BIG (2 * KC * LDA * 4)

__global__ __launch_bounds__(256) void big_kernel(float* __restrict__ out)
{
    extern __shared__ __align__(16) float sm[];
    float* As = sm;               // [144][68]  (k-major rows, i inner)
    float* Bs = sm + KC * LDA;    // [144][68]  (k-major rows, j inner)

    const int tid = threadIdx.x;
    const int tx = tid & 15;
    const int ty = tid >> 4;
    const int ibase = blockIdx.x * TI;
    const int o = blockIdx.y;
    const int b = blockIdx.z;
    const int delta = (o / 3 - 1) * Ww + (o % 3 - 1);

    const float* P1b = g_P1 + b * HS * Sp;
    const float* P2b = g_P2 + b * HS * Sp;
    float* outBO = out + (size_t)(b * On + o) * HS * HS;

    // Load A tile (64 i x 144 k), gathered via center index sc(k) = (1+k/12)*14 + 1 + k%12
    for (int l = tid; l < TI * KC; l += 256) {
        int i = l / KC;
        int k = l - i * KC;
        int s = (1 + k / 12) * Ww + 1 + (k % 12);
        As[k * LDA + i] = P1b[(ibase + i) * Sp + s];
    }

    float ssq[4] = {0.f, 0.f, 0.f, 0.f};

    for (int jt = 0; jt < HS / TJ; ++jt) {
        int jbase = jt * TJ;
        __syncthreads();  // prior compute done reading Bs (and A-load visible on first iter)
        for (int l = tid; l < TJ * KC; l += 256) {
            int j = l / KC;
            int k = l - j * KC;
            int s = (1 + k / 12) * Ww + 1 + (k % 12) + delta;
            Bs[k * LDA + j] = P2b[(jbase + j) * Sp + s];
        }
        __syncthreads();

        float acc[4][4] = {};
        #pragma unroll 4
        for (int k = 0; k < KC; ++k) {
            float4 a  = *(const float4*)(As + k * LDA + ty * 4);
            float4 bv = *(const float4*)(Bs + k * LDA + tx * 4);
            acc[0][0] += a.x * bv.x; acc[0][1] += a.x * bv.y; acc[0][2] += a.x * bv.z; acc[0][3] += a.x * bv.w;
            acc[1][0] += a.y * bv.x; acc[1][1] += a.y * bv.y; acc[1][2] += a.y * bv.z; acc[1][3] += a.y * bv.w;
            acc[2][0] += a.z * bv.x; acc[2][1] += a.z * bv.y; acc[2][2] += a.z * bv.z; acc[2][3] += a.z * bv.w;
            acc[3][0] += a.w * bv.x; acc[3][1] += a.w * bv.y; acc[3][2] += a.w * bv.z; acc[3][3] += a.w * bv.w;
        }

        #pragma unroll
        for (int u = 0; u < 4; ++u) {
            float4 v = make_float4(acc[u][0], acc[u][1], acc[u][2], acc[u][3]);
            ssq[u] += v.x * v.x + v.y * v.y + v.z * v.z + v.w * v.w;
            *(float4*)(outBO + (size_t)(ibase + ty * 4 + u) * HS + jbase + tx * 4) = v;
        }
    }

    // Reduce ssq across the 16 tx lanes sharing the same i rows (xor<16 stays in half-warp)
    #pragma unroll
    for (int u = 0; u < 4; ++u) {
        float v = ssq[u];
        #pragma unroll
        for (int off = 8; off >= 1; off >>= 1)
            v += __shfl_xor_sync(0xffffffffu, v, off);
        if (tx == 0)
            g_ssq[(b * On + o) * HS + ibase + ty * 4 + u] = v;
    }
}

// ---------------------------------------------------------------------------
// norm: out[row][:] *= 1 / max(sqrt(ssq[row]), 1e-12), float4-vectorized.
// ---------------------------------------------------------------------------
__global__ __launch_bounds__(256) void norm_kernel(float* __restrict__ out)
{
    const int N4 = Bn * On * HS * (HS / 4);   // 18,874,368
    int idx = blockIdx.x * 256 + threadIdx.x;
    if (idx >= N4) return;
    int row = idx >> 8;                        // 256 float4 per 1024-wide row
    float sc = 1.f / fmaxf(sqrtf(g_ssq[row]), 1e-12f);
    float4 v = ((float4*)out)[idx];
    v.x *= sc; v.y *= sc; v.z *= sc; v.w *= sc;
    ((float4*)out)[idx] = v;
}

// ---------------------------------------------------------------------------
extern "C" void kernel_launch(void* const* d_in, const int* in_sizes, int n_in,
                              void* d_out, int out_size)
{
    const float* x  = (const float*)d_in[0];
    const float* w1 = (const float*)d_in[1];
    const float* b1 = (const float*)d_in[2];
    const float* w2 = (const float*)d_in[3];
    const float* b2 = (const float*)d_in[4];
    float* out = (float*)d_out;

    cudaFuncSetAttribute(big_kernel, cudaFuncAttributeMaxDynamicSharedMemorySize, SMEM_BIG);

    dim3 tpb(256);
    proj_kernel<<<dim3(7, 16, Bn), tpb>>>(x, w1, b1, 0);  // -> g_P1
    proj_kernel<<<dim3(7, 16, Bn), tpb>>>(x, w2, b2, 1);  // -> g_P2
    big_kernel<<<dim3(HS / TI, On, Bn), tpb, SMEM_BIG>>>(out);
    norm_kernel<<<(Bn * On * HS * (HS / 4) + 255) / 256, tpb>>>(out);
}

// round 3
// speedup vs baseline: 1.7557x; 1.7557x over previous
#include <cuda_runtime.h>
#include <cstdint>

// Problem constants
#define Bn 8
#define Cc 512
#define Ww 14
#define HS 1024
#define Sp 196      // 14*14
#define KC 144      // 12*12 interior centers
#define On 9        // 3x3 offsets
#define NK 18       // 144 / 8 k-steps

// Scratch (__device__ globals: allocation-free rule)
__device__ float g_P1[Bn * HS * Sp];
__device__ float g_P2[Bn * HS * Sp];
__device__ float g_Ag[(size_t)Bn * HS * KC];          // gathered center proj (tf32-rounded)
__device__ float g_Bg[(size_t)Bn * On * HS * KC];     // gathered side proj (tf32-rounded)

// ---------------------------------------------------------------------------
// proj: P[b][h][s] = sum_c w[h][c] * x[b][c][s] + bias[h]   (unchanged, passing)
// ---------------------------------------------------------------------------
__global__ __launch_bounds__(256) void proj_kernel(const float* __restrict__ x,
                                                   const float* __restrict__ w,
                                                   const float* __restrict__ bias,
                                                   int which)
{
    __shared__ __align__(16) float Wst[32 * 68];
    __shared__ __align__(16) float Xs[32 * 33];

    float* outP = which ? g_P2 : g_P1;
    const int tid = threadIdx.x;
    const int tx = tid & 15;
    const int ty = tid >> 4;
    const int sbase = blockIdx.x * 32;
    const int hbase = blockIdx.y * 64;
    const int b = blockIdx.z;

    float acc[4][2] = {};
    for (int cb = 0; cb < Cc; cb += 32) {
        #pragma unroll
        for (int r = 0; r < 8; ++r) {
            int l = tid + r * 256;
            int h = l >> 5, c = l & 31;
            Wst[c * 68 + h] = w[(hbase + h) * Cc + cb + c];
        }
        #pragma unroll
        for (int r = 0; r < 4; ++r) {
            int l = tid + r * 256;
            int c = l >> 5, s = l & 31;
            int sg = sbase + s;
            Xs[c * 33 + s] = (sg < Sp) ? x[(b * Cc + cb + c) * Sp + sg] : 0.f;
        }
        __syncthreads();
        #pragma unroll 8
        for (int c = 0; c < 32; ++c) {
            float4 a = *(const float4*)(Wst + c * 68 + ty * 4);
            float b0 = Xs[c * 33 + tx * 2];
            float b1 = Xs[c * 33 + tx * 2 + 1];
            acc[0][0] += a.x * b0; acc[0][1] += a.x * b1;
            acc[1][0] += a.y * b0; acc[1][1] += a.y * b1;
            acc[2][0] += a.z * b0; acc[2][1] += a.z * b1;
            acc[3][0] += a.w * b0; acc[3][1] += a.w * b1;
        }
        __syncthreads();
    }
    #pragma unroll
    for (int u = 0; u < 4; ++u) {
        int h = hbase + ty * 4 + u;
        float bb = bias[h];
        #pragma unroll
        for (int v = 0; v < 2; ++v) {
            int s = sbase + tx * 2 + v;
            if (s < Sp) outP[(b * HS + h) * Sp + s] = acc[u][v] + bb;
        }
    }
}

// ---------------------------------------------------------------------------
// gather: build gathered operand matrices, pre-rounded to tf32.
// Ag[b*HS+i][k] = tf32(P1[b,i,sc(k)]);  Bg[(b*9+o)*HS+j][k] = tf32(P2[b,j,sc(k)+delta_o])
// ---------------------------------------------------------------------------
__global__ __launch_bounds__(160) void gather_kernel()
{
    int row = blockIdx.x;
    int k = threadIdx.x;
    if (k >= KC) return;
    int ky = k / 12, kx = k - ky * 12;
    float v;
    if (row < Bn * HS) {
        int s = (1 + ky) * Ww + 1 + kx;
        v = g_P1[(size_t)row * Sp + s];
        asm("cvt.rna.tf32.f32 %0, %0;" : "+f"(v));
        g_Ag[(size_t)row * KC + k] = v;
    } else {
        int r2 = row - Bn * HS;              // b*9*1024 + o*1024 + j
        int b = r2 / (On * HS);
        int rem = r2 - b * On * HS;
        int o = rem >> 10;
        int j = rem & 1023;
        int delta = (o / 3 - 1) * Ww + (o % 3 - 1);
        int s = (1 + ky) * Ww + 1 + kx + delta;
        v = g_P2[((size_t)b * HS + j) * Sp + s];
        asm("cvt.rna.tf32.f32 %0, %0;" : "+f"(v));
        g_Bg[(size_t)r2 * KC + k] = v;
    }
}

// ---------------------------------------------------------------------------
// big_mma: cofe GEMM on tensor cores via mma.sync m16n8k8 tf32 + fused norm.
// CTA = (i-tile 128, o, b), 256 threads = 8 warps (2 m x 4 n), warp tile 64x32.
// A tile (128x144) resident all 8 j-tiles; B tile reloaded per j-tile.
// Per-row ssq accumulated in regs -> shfl -> shared atomics; final in-place
// rescale re-reads the CTA's own (L2-hot) 512KB output tile.
// ---------------------------------------------------------------------------
#define LDP 148                    // smem row pitch (floats): conflict-free, 16B-aligned
#define SC_OFF 0                   // s_scale[128]  (512 B)
#define SQ_OFF 512                 // s_ssq[128]    (512 B)
#define A_OFF 1024
#define B_OFF (A_OFF + 128 * LDP * 4)       // 1024 + 75776 = 76800
#define SMEM_MMA (B_OFF + 128 * LDP * 4)    // 152576

__device__ __forceinline__ void mma_tf32(float* c, const uint32_t* a, const uint32_t* b) {
    asm volatile(
        "mma.sync.aligned.m16n8k8.row.col.f32.tf32.tf32.f32 "
        "{%0,%1,%2,%3}, {%4,%5,%6,%7}, {%8,%9}, {%0,%1,%2,%3};"
        : "+f"(c[0]), "+f"(c[1]), "+f"(c[2]), "+f"(c[3])
        : "r"(a[0]), "r"(a[1]), "r"(a[2]), "r"(a[3]), "r"(b[0]), "r"(b[1]));
}

__global__ __launch_bounds__(256, 1) void big_mma(float* __restrict__ out)
{
    extern __shared__ __align__(16) char sm[];
    float* s_scale = (float*)(sm + SC_OFF);
    float* s_ssq   = (float*)(sm + SQ_OFF);
    float* As      = (float*)(sm + A_OFF);
    float* Bs      = (float*)(sm + B_OFF);
    const uint32_t* As_u = (const uint32_t*)As;
    const uint32_t* Bs_u = (const uint32_t*)Bs;

    const int tid = threadIdx.x;
    const int wid = tid >> 5;
    const int lane = tid & 31;
    const int gid = lane >> 2;          // groupID (0..7)
    const int tg = lane & 3;            // threadID_in_group
    const int wm = wid & 1;             // warp row (2)
    const int wn = wid >> 1;            // warp col (4)

    const int ibase = blockIdx.x * 128;
    const int o = blockIdx.y;
    const int b = blockIdx.z;

    const float* Ab = g_Ag + ((size_t)b * HS + ibase) * KC;
    const float* Bb = g_Bg + ((size_t)(b * On + o) * HS) * KC;
    float* outBO = out + (size_t)(b * On + o) * HS * HS;

    // Load A tile: 128 rows x 144 floats (36 float4 per row)
    for (int l = tid; l < 128 * 36; l += 256) {
        int r = l / 36, k4 = l - r * 36;
        *(float4*)(As + r * LDP + k4 * 4) = *(const float4*)(Ab + (size_t)r * KC + k4 * 4);
    }
    if (tid < 128) s_ssq[tid] = 0.f;

    float ssqr[4][2] = {};              // per (mt, row-half) partial sum of squares

    for (int jt = 0; jt < 8; ++jt) {
        __syncthreads();                // Bs free (and A/ssq init visible on iter 0)
        const float* Bt = Bb + (size_t)(jt * 128) * KC;
        for (int l = tid; l < 128 * 36; l += 256) {
            int r = l / 36, k4 = l - r * 36;
            *(float4*)(Bs + r * LDP + k4 * 4) = *(const float4*)(Bt + (size_t)r * KC + k4 * 4);
        }
        __syncthreads();

        float acc[4][4][4] = {};        // [mt][nt][c0..c3]

        #pragma unroll 3
        for (int ks = 0; ks < NK; ++ks) {
            const int k0 = ks * 8 + tg;
            uint32_t af[4][4], bf[4][2];
            #pragma unroll
            for (int mt = 0; mt < 4; ++mt) {
                int r = wm * 64 + mt * 16 + gid;
                af[mt][0] = As_u[r * LDP + k0];
                af[mt][1] = As_u[(r + 8) * LDP + k0];
                af[mt][2] = As_u[r * LDP + k0 + 4];
                af[mt][3] = As_u[(r + 8) * LDP + k0 + 4];
            }
            #pragma unroll
            for (int nt = 0; nt < 4; ++nt) {
                int c = wn * 32 + nt * 8 + gid;
                bf[nt][0] = Bs_u[c * LDP + k0];
                bf[nt][1] = Bs_u[c * LDP + k0 + 4];
            }
            #pragma unroll
            for (int mt = 0; mt < 4; ++mt)
                #pragma unroll
                for (int nt = 0; nt < 4; ++nt)
                    mma_tf32(acc[mt][nt], af[mt], bf[nt]);
        }

        // Write unnormalized tile + accumulate ssq
        #pragma unroll
        for (int mt = 0; mt < 4; ++mt) {
            int r0 = ibase + wm * 64 + mt * 16 + gid;
            #pragma unroll
            for (int nt = 0; nt < 4; ++nt) {
                int c = jt * 128 + wn * 32 + nt * 8 + tg * 2;
                float* p0 = outBO + (size_t)r0 * HS + c;
                float* p1 = outBO + (size_t)(r0 + 8) * HS + c;
                float c0 = acc[mt][nt][0], c1 = acc[mt][nt][1];
                float c2 = acc[mt][nt][2], c3 = acc[mt][nt][3];
                *(float2*)p0 = make_float2(c0, c1);
                *(float2*)p1 = make_float2(c2, c3);
                ssqr[mt][0] += c0 * c0 + c1 * c1;
                ssqr[mt][1] += c2 * c2 + c3 * c3;
            }
        }
    }

    // Reduce ssq over the 4 lanes of each group (tg), then across n-warps via smem atomics
    #pragma unroll
    for (int mt = 0; mt < 4; ++mt)
        #pragma unroll
        for (int h = 0; h < 2; ++h) {
            float v = ssqr[mt][h];
            v += __shfl_xor_sync(0xffffffffu, v, 1);
            v += __shfl_xor_sync(0xffffffffu, v, 2);
            if (tg == 0)
                atomicAdd(&s_ssq[wm * 64 + mt * 16 + h * 8 + gid], v);
        }
    __syncthreads();
    if (tid < 128)
        s_scale[tid] = 1.f / fmaxf(sqrtf(s_ssq[tid]), 1e-12f);
    __syncthreads();

    // In-place rescale of this CTA's 128x1024 tile (L2-hot re-read)
    for (int l = tid; l < 128 * 256; l += 256) {
        int r = l >> 8, c4 = l & 255;
        float sc = s_scale[r];
        float4* p = (float4*)(outBO + (size_t)(ibase + r) * HS) + c4;
        float4 v = *p;
        v.x *= sc; v.y *= sc; v.z *= sc; v.w *= sc;
        *p = v;
    }
}

// ---------------------------------------------------------------------------
extern "C" void kernel_launch(void* const* d_in, const int* in_sizes, int n_in,
                              void* d_out, int out_size)
{
    const float* x  = (const float*)d_in[0];
    const float* w1 = (const float*)d_in[1];
    const float* b1 = (const float*)d_in[2];
    const float* w2 = (const float*)d_in[3];
    const float* b2 = (const float*)d_in[4];
    float* out = (float*)d_out;

    cudaFuncSetAttribute(big_mma, cudaFuncAttributeMaxDynamicSharedMemorySize, SMEM_MMA);

    dim3 tpb(256);
    proj_kernel<<<dim3(7, 16, Bn), tpb>>>(x, w1, b1, 0);
    proj_kernel<<<dim3(7, 16, Bn), tpb>>>(x, w2, b2, 1);
    gather_kernel<<<Bn * HS + Bn * On * HS, 160>>>();
    big_mma<<<dim3(HS / 128, On, Bn), tpb, SMEM_MMA>>>(out);
}

// round 4
// speedup vs baseline: 1.9974x; 1.1376x over previous
#include <cuda_runtime.h>
#include <cstdint>

// Problem constants
#define Bn 8
#define Cc 512
#define Ww 14
#define HS 1024
#define Sp 196      // 14*14
#define KC 144      // 12*12 interior centers
#define On 9        // 3x3 offsets
#define NK 18       // 144 / 8 k-steps

// Scratch (__device__ globals: allocation-free rule)
__device__ float g_P1[Bn * HS * Sp];
__device__ float g_P2[Bn * HS * Sp];
__device__ float g_Ag[(size_t)Bn * HS * KC];          // gathered center proj (tf32-rounded)
__device__ float g_Bg[(size_t)Bn * On * HS * KC];     // gathered side proj (tf32-rounded)

// ---------------------------------------------------------------------------
// proj: P[b][h][s] = sum_c w[h][c] * x[b][c][s] + bias[h]   (unchanged, passing)
// ---------------------------------------------------------------------------
__global__ __launch_bounds__(256) void proj_kernel(const float* __restrict__ x,
                                                   const float* __restrict__ w,
                                                   const float* __restrict__ bias,
                                                   int which)
{
    __shared__ __align__(16) float Wst[32 * 68];
    __shared__ __align__(16) float Xs[32 * 33];

    float* outP = which ? g_P2 : g_P1;
    const int tid = threadIdx.x;
    const int tx = tid & 15;
    const int ty = tid >> 4;
    const int sbase = blockIdx.x * 32;
    const int hbase = blockIdx.y * 64;
    const int b = blockIdx.z;

    float acc[4][2] = {};
    for (int cb = 0; cb < Cc; cb += 32) {
        #pragma unroll
        for (int r = 0; r < 8; ++r) {
            int l = tid + r * 256;
            int h = l >> 5, c = l & 31;
            Wst[c * 68 + h] = w[(hbase + h) * Cc + cb + c];
        }
        #pragma unroll
        for (int r = 0; r < 4; ++r) {
            int l = tid + r * 256;
            int c = l >> 5, s = l & 31;
            int sg = sbase + s;
            Xs[c * 33 + s] = (sg < Sp) ? x[(b * Cc + cb + c) * Sp + sg] : 0.f;
        }
        __syncthreads();
        #pragma unroll 8
        for (int c = 0; c < 32; ++c) {
            float4 a = *(const float4*)(Wst + c * 68 + ty * 4);
            float b0 = Xs[c * 33 + tx * 2];
            float b1 = Xs[c * 33 + tx * 2 + 1];
            acc[0][0] += a.x * b0; acc[0][1] += a.x * b1;
            acc[1][0] += a.y * b0; acc[1][1] += a.y * b1;
            acc[2][0] += a.z * b0; acc[2][1] += a.z * b1;
            acc[3][0] += a.w * b0; acc[3][1] += a.w * b1;
        }
        __syncthreads();
    }
    #pragma unroll
    for (int u = 0; u < 4; ++u) {
        int h = hbase + ty * 4 + u;
        float bb = bias[h];
        #pragma unroll
        for (int v = 0; v < 2; ++v) {
            int s = sbase + tx * 2 + v;
            if (s < Sp) outP[(b * HS + h) * Sp + s] = acc[u][v] + bb;
        }
    }
}

// ---------------------------------------------------------------------------
// gather: build gathered operand matrices, pre-rounded to tf32.
// ---------------------------------------------------------------------------
__global__ __launch_bounds__(160) void gather_kernel()
{
    int row = blockIdx.x;
    int k = threadIdx.x;
    if (k >= KC) return;
    int ky = k / 12, kx = k - ky * 12;
    float v;
    if (row < Bn * HS) {
        int s = (1 + ky) * Ww + 1 + kx;
        v = g_P1[(size_t)row * Sp + s];
        asm("cvt.rna.tf32.f32 %0, %0;" : "+f"(v));
        g_Ag[(size_t)row * KC + k] = v;
    } else {
        int r2 = row - Bn * HS;
        int b = r2 / (On * HS);
        int rem = r2 - b * On * HS;
        int o = rem >> 10;
        int j = rem & 1023;
        int delta = (o / 3 - 1) * Ww + (o % 3 - 1);
        int s = (1 + ky) * Ww + 1 + kx + delta;
        v = g_P2[((size_t)b * HS + j) * Sp + s];
        asm("cvt.rna.tf32.f32 %0, %0;" : "+f"(v));
        g_Bg[(size_t)r2 * KC + k] = v;
    }
}

// ---------------------------------------------------------------------------
// big_mma: cofe GEMM via mma.sync m16n8k8 tf32 + fused norm.
// CTA = (i-tile 256, o, b), 512 threads = 16 warps (4 m x 4 n), warp tile 64x32.
// A tile (256x144) resident; B tile (128x144) reloaded per j-tile (8 tiles).
// ---------------------------------------------------------------------------
#define LDP 148                    // smem row pitch (floats)
#define SC_OFF 0                   // s_scale[256]  (1 KB)
#define SQ_OFF 1024                // s_ssq[256]    (1 KB)
#define A_OFF 2048
#define B_OFF (A_OFF + 256 * LDP * 4)       // 2048 + 151552 = 153600
#define SMEM_MMA (B_OFF + 128 * LDP * 4)    // 229376

__device__ __forceinline__ void mma_tf32(float* c, const uint32_t* a, const uint32_t* b) {
    asm volatile(
        "mma.sync.aligned.m16n8k8.row.col.f32.tf32.tf32.f32 "
        "{%0,%1,%2,%3}, {%4,%5,%6,%7}, {%8,%9}, {%0,%1,%2,%3};"
        : "+f"(c[0]), "+f"(c[1]), "+f"(c[2]), "+f"(c[3])
        : "r"(a[0]), "r"(a[1]), "r"(a[2]), "r"(a[3]), "r"(b[0]), "r"(b[1]));
}

__global__ __launch_bounds__(512, 1) void big_mma(float* __restrict__ out)
{
    extern __shared__ __align__(16) char sm[];
    float* s_scale = (float*)(sm + SC_OFF);
    float* s_ssq   = (float*)(sm + SQ_OFF);
    float* As      = (float*)(sm + A_OFF);
    float* Bs      = (float*)(sm + B_OFF);
    const uint32_t* As_u = (const uint32_t*)As;
    const uint32_t* Bs_u = (const uint32_t*)Bs;

    const int tid = threadIdx.x;
    const int wid = tid >> 5;
    const int lane = tid & 31;
    const int gid = lane >> 2;          // groupID (0..7)
    const int tg = lane & 3;            // threadID_in_group
    const int wm = wid & 3;             // warp row (4): 64-row band
    const int wn = wid >> 2;            // warp col (4): 32-col band

    const int ibase = blockIdx.x * 256;
    const int o = blockIdx.y;
    const int b = blockIdx.z;

    const float* Ab = g_Ag + ((size_t)b * HS + ibase) * KC;
    const float* Bb = g_Bg + ((size_t)(b * On + o) * HS) * KC;
    float* outBO = out + (size_t)(b * On + o) * HS * HS;

    // Load A tile: 256 rows x 144 floats (36 float4 per row)
    for (int l = tid; l < 256 * 36; l += 512) {
        int r = l / 36, k4 = l - r * 36;
        *(float4*)(As + r * LDP + k4 * 4) = *(const float4*)(Ab + (size_t)r * KC + k4 * 4);
    }
    if (tid < 256) s_ssq[tid] = 0.f;

    float ssqr[4][2] = {};              // per (mt, row-half) partial sum of squares

    for (int jt = 0; jt < 8; ++jt) {
        __syncthreads();                // Bs free (and A/ssq init visible on iter 0)
        const float* Bt = Bb + (size_t)(jt * 128) * KC;
        for (int l = tid; l < 128 * 36; l += 512) {
            int r = l / 36, k4 = l - r * 36;
            *(float4*)(Bs + r * LDP + k4 * 4) = *(const float4*)(Bt + (size_t)r * KC + k4 * 4);
        }
        __syncthreads();

        float acc[4][4][4] = {};        // [mt][nt][c0..c3]

        #pragma unroll 2
        for (int ks = 0; ks < NK; ++ks) {
            const int k0 = ks * 8 + tg;
            uint32_t af[4][4], bf[4][2];
            #pragma unroll
            for (int mt = 0; mt < 4; ++mt) {
                int r = wm * 64 + mt * 16 + gid;
                af[mt][0] = As_u[r * LDP + k0];
                af[mt][1] = As_u[(r + 8) * LDP + k0];
                af[mt][2] = As_u[r * LDP + k0 + 4];
                af[mt][3] = As_u[(r + 8) * LDP + k0 + 4];
            }
            #pragma unroll
            for (int nt = 0; nt < 4; ++nt) {
                int c = wn * 32 + nt * 8 + gid;
                bf[nt][0] = Bs_u[c * LDP + k0];
                bf[nt][1] = Bs_u[c * LDP + k0 + 4];
            }
            #pragma unroll
            for (int mt = 0; mt < 4; ++mt)
                #pragma unroll
                for (int nt = 0; nt < 4; ++nt)
                    mma_tf32(acc[mt][nt], af[mt], bf[nt]);
        }

        // Write unnormalized tile + accumulate ssq
        #pragma unroll
        for (int mt = 0; mt < 4; ++mt) {
            int r0 = ibase + wm * 64 + mt * 16 + gid;
            #pragma unroll
            for (int nt = 0; nt < 4; ++nt) {
                int c = jt * 128 + wn * 32 + nt * 8 + tg * 2;
                float* p0 = outBO + (size_t)r0 * HS + c;
                float* p1 = outBO + (size_t)(r0 + 8) * HS + c;
                float c0 = acc[mt][nt][0], c1 = acc[mt][nt][1];
                float c2 = acc[mt][nt][2], c3 = acc[mt][nt][3];
                *(float2*)p0 = make_float2(c0, c1);
                *(float2*)p1 = make_float2(c2, c3);
                ssqr[mt][0] += c0 * c0 + c1 * c1;
                ssqr[mt][1] += c2 * c2 + c3 * c3;
            }
        }
    }

    // Reduce ssq over the 4 tg lanes, then across n-warps via smem atomics
    #pragma unroll
    for (int mt = 0; mt < 4; ++mt)
        #pragma unroll
        for (int h = 0; h < 2; ++h) {
            float v = ssqr[mt][h];
            v += __shfl_xor_sync(0xffffffffu, v, 1);
            v += __shfl_xor_sync(0xffffffffu, v, 2);
            if (tg == 0)
                atomicAdd(&s_ssq[wm * 64 + mt * 16 + h * 8 + gid], v);
        }
    __syncthreads();
    if (tid < 256)
        s_scale[tid] = 1.f / fmaxf(sqrtf(s_ssq[tid]), 1e-12f);
    __syncthreads();

    // In-place rescale of this CTA's 256x1024 tile (L2-hot re-read)
    for (int l = tid; l < 256 * 256; l += 512) {
        int r = l >> 8, c4 = l & 255;
        float sc = s_scale[r];
        float4* p = (float4*)(outBO + (size_t)(ibase + r) * HS) + c4;
        float4 v = *p;
        v.x *= sc; v.y *= sc; v.z *= sc; v.w *= sc;
        *p = v;
    }
}

// ---------------------------------------------------------------------------
extern "C" void kernel_launch(void* const* d_in, const int* in_sizes, int n_in,
                              void* d_out, int out_size)
{
    const float* x  = (const float*)d_in[0];
    const float* w1 = (const float*)d_in[1];
    const float* b1 = (const float*)d_in[2];
    const float* w2 = (const float*)d_in[3];
    const float* b2 = (const float*)d_in[4];
    float* out = (float*)d_out;

    cudaFuncSetAttribute(big_mma, cudaFuncAttributeMaxDynamicSharedMemorySize, SMEM_MMA);

    dim3 tpb(256);
    proj_kernel<<<dim3(7, 16, Bn), tpb>>>(x, w1, b1, 0);
    proj_kernel<<<dim3(7, 16, Bn), tpb>>>(x, w2, b2, 1);
    gather_kernel<<<Bn * HS + Bn * On * HS, 160>>>();
    big_mma<<<dim3(HS / 256, On, Bn), dim3(512), SMEM_MMA>>>(out);
}

// round 5
// speedup vs baseline: 2.0151x; 1.0088x over previous
#include <cuda_runtime.h>
#include <cstdint>

// Problem constants
#define Bn 8
#define Cc 512
#define Ww 14
#define HS 1024
#define Sp 196      // 14*14
#define KC 144      // 12*12 interior centers
#define On 9        // 3x3 offsets
#define NK 18       // 144 / 8 k-steps

// Scratch (__device__ globals: allocation-free rule)
__device__ float g_P1[Bn * HS * Sp];
__device__ float g_P2[Bn * HS * Sp];
__device__ float g_Ag[(size_t)Bn * HS * KC];          // gathered, tf32-rounded, k-permuted
__device__ float g_Bg[(size_t)Bn * On * HS * KC];     // gathered, tf32-rounded, k-permuted

// ---------------------------------------------------------------------------
// proj: P[b][h][s] = sum_c w[h][c] * x[b][c][s] + bias[h]   (unchanged, passing)
// ---------------------------------------------------------------------------
__global__ __launch_bounds__(256) void proj_kernel(const float* __restrict__ x,
                                                   const float* __restrict__ w,
                                                   const float* __restrict__ bias,
                                                   int which)
{
    __shared__ __align__(16) float Wst[32 * 68];
    __shared__ __align__(16) float Xs[32 * 33];

    float* outP = which ? g_P2 : g_P1;
    const int tid = threadIdx.x;
    const int tx = tid & 15;
    const int ty = tid >> 4;
    const int sbase = blockIdx.x * 32;
    const int hbase = blockIdx.y * 64;
    const int b = blockIdx.z;

    float acc[4][2] = {};
    for (int cb = 0; cb < Cc; cb += 32) {
        #pragma unroll
        for (int r = 0; r < 8; ++r) {
            int l = tid + r * 256;
            int h = l >> 5, c = l & 31;
            Wst[c * 68 + h] = w[(hbase + h) * Cc + cb + c];
        }
        #pragma unroll
        for (int r = 0; r < 4; ++r) {
            int l = tid + r * 256;
            int c = l >> 5, s = l & 31;
            int sg = sbase + s;
            Xs[c * 33 + s] = (sg < Sp) ? x[(b * Cc + cb + c) * Sp + sg] : 0.f;
        }
        __syncthreads();
        #pragma unroll 8
        for (int c = 0; c < 32; ++c) {
            float4 a = *(const float4*)(Wst + c * 68 + ty * 4);
            float b0 = Xs[c * 33 + tx * 2];
            float b1 = Xs[c * 33 + tx * 2 + 1];
            acc[0][0] += a.x * b0; acc[0][1] += a.x * b1;
            acc[1][0] += a.y * b0; acc[1][1] += a.y * b1;
            acc[2][0] += a.z * b0; acc[2][1] += a.z * b1;
            acc[3][0] += a.w * b0; acc[3][1] += a.w * b1;
        }
        __syncthreads();
    }
    #pragma unroll
    for (int u = 0; u < 4; ++u) {
        int h = hbase + ty * 4 + u;
        float bb = bias[h];
        #pragma unroll
        for (int v = 0; v < 2; ++v) {
            int s = sbase + tx * 2 + v;
            if (s < Sp) outP[(b * HS + h) * Sp + s] = acc[u][v] + bb;
        }
    }
}

// ---------------------------------------------------------------------------
// gather: build gathered operands, tf32-rounded, with k-chunk permutation
// [0,4,1,5,2,6,3,7] so the MMA fragment pair (k0, k0+4) is a contiguous float2.
// thread k -> dest position ks*8 + (k%4)*2 + ((k%8)/4)
// ---------------------------------------------------------------------------
__global__ __launch_bounds__(160) void gather_kernel()
{
    int row = blockIdx.x;
    int k = threadIdx.x;
    if (k >= KC) return;
    int ky = k / 12, kx = k - ky * 12;
    int ks = k >> 3, kk = k & 7;
    int dpos = ks * 8 + (kk & 3) * 2 + (kk >> 2);
    float v;
    if (row < Bn * HS) {
        int s = (1 + ky) * Ww + 1 + kx;
        v = g_P1[(size_t)row * Sp + s];
        asm("cvt.rna.tf32.f32 %0, %0;" : "+f"(v));
        g_Ag[(size_t)row * KC + dpos] = v;
    } else {
        int r2 = row - Bn * HS;
        int b = r2 / (On * HS);
        int rem = r2 - b * On * HS;
        int o = rem >> 10;
        int j = rem & 1023;
        int delta = (o / 3 - 1) * Ww + (o % 3 - 1);
        int s = (1 + ky) * Ww + 1 + kx + delta;
        v = g_P2[((size_t)b * HS + j) * Sp + s];
        asm("cvt.rna.tf32.f32 %0, %0;" : "+f"(v));
        g_Bg[(size_t)r2 * KC + dpos] = v;
    }
}

// ---------------------------------------------------------------------------
// big_mma: cofe GEMM via mma.sync m16n8k8 tf32 + fused norm.
// CTA = (i-tile 256, o, b), 512 threads = 16 warps (4m x 4n), warp tile 64x32.
// float2 fragment loads (permuted layout) + 2-stage k-pipeline.
// ---------------------------------------------------------------------------
#define LDPA 152                   // A pitch: conflict-free LDS.64 pattern
#define LDPB 148                   // B pitch
#define A_OFF 0
#define B_OFF (256 * LDPA * 4)                  // 155648
#define SMEM_MMA (B_OFF + 128 * LDPB * 4)       // 231424
// ssq/scale alias the dead B region after the MMA loop:
#define SQ_OFF B_OFF
#define SC_OFF (B_OFF + 1024)

__device__ __forceinline__ void mma_tf32(float* c, uint32_t a0, uint32_t a1,
                                         uint32_t a2, uint32_t a3,
                                         uint32_t b0, uint32_t b1) {
    asm volatile(
        "mma.sync.aligned.m16n8k8.row.col.f32.tf32.tf32.f32 "
        "{%0,%1,%2,%3}, {%4,%5,%6,%7}, {%8,%9}, {%0,%1,%2,%3};"
        : "+f"(c[0]), "+f"(c[1]), "+f"(c[2]), "+f"(c[3])
        : "r"(a0), "r"(a1), "r"(a2), "r"(a3), "r"(b0), "r"(b1));
}

__global__ __launch_bounds__(512, 1) void big_mma(float* __restrict__ out)
{
    extern __shared__ __align__(16) char sm[];
    float* As = (float*)(sm + A_OFF);
    float* Bs = (float*)(sm + B_OFF);
    float* s_ssq = (float*)(sm + SQ_OFF);
    float* s_scale = (float*)(sm + SC_OFF);

    const int tid = threadIdx.x;
    const int wid = tid >> 5;
    const int lane = tid & 31;
    const int gid = lane >> 2;          // groupID (0..7)
    const int tg = lane & 3;            // threadID_in_group
    const int wm = wid & 3;             // warp row (4): 64-row band
    const int wn = wid >> 2;            // warp col (4): 32-col band

    const int ibase = blockIdx.x * 256;
    const int o = blockIdx.y;
    const int b = blockIdx.z;

    const float* Ab = g_Ag + ((size_t)b * HS + ibase) * KC;
    const float* Bb = g_Bg + ((size_t)(b * On + o) * HS) * KC;
    float* outBO = out + (size_t)(b * On + o) * HS * HS;

    // Load A tile: 256 rows x 144 floats (36 float4 per row)
    for (int l = tid; l < 256 * 36; l += 512) {
        int r = l / 36, k4 = l - r * 36;
        *(float4*)(As + r * LDPA + k4 * 4) = *(const float4*)(Ab + (size_t)r * KC + k4 * 4);
    }

    // Per-thread fragment base pointers (permuted layout: float2 = (k0, k0+4))
    const float* Apt[4];
    const float* Bpt[4];
    #pragma unroll
    for (int mt = 0; mt < 4; ++mt)
        Apt[mt] = As + (wm * 64 + mt * 16 + gid) * LDPA + tg * 2;
    #pragma unroll
    for (int nt = 0; nt < 4; ++nt)
        Bpt[nt] = Bs + (wn * 32 + nt * 8 + gid) * LDPB + tg * 2;

    float ssqr[4][2] = {};

    #pragma unroll 1
    for (int jt = 0; jt < 8; ++jt) {
        __syncthreads();                // Bs free (A load visible on iter 0)
        const float* Bt = Bb + (size_t)(jt * 128) * KC;
        for (int l = tid; l < 128 * 36; l += 512) {
            int r = l / 36, k4 = l - r * 36;
            *(float4*)(Bs + r * LDPB + k4 * 4) = *(const float4*)(Bt + (size_t)r * KC + k4 * 4);
        }
        __syncthreads();

        float acc[4][4][4] = {};
        float2 a0[4][2], a1[4][2], b0[4], b1[4];

        // prologue: stage 0 <- ks 0
        #pragma unroll
        for (int mt = 0; mt < 4; ++mt) {
            a0[mt][0] = *(const float2*)(Apt[mt]);
            a0[mt][1] = *(const float2*)(Apt[mt] + 8 * LDPA);
        }
        #pragma unroll
        for (int nt = 0; nt < 4; ++nt)
            b0[nt] = *(const float2*)(Bpt[nt]);

        #pragma unroll
        for (int ks = 0; ks < NK; ks += 2) {
            // prefetch stage 1 <- ks+1
            #pragma unroll
            for (int mt = 0; mt < 4; ++mt) {
                a1[mt][0] = *(const float2*)(Apt[mt] + (ks + 1) * 8);
                a1[mt][1] = *(const float2*)(Apt[mt] + (ks + 1) * 8 + 8 * LDPA);
            }
            #pragma unroll
            for (int nt = 0; nt < 4; ++nt)
                b1[nt] = *(const float2*)(Bpt[nt] + (ks + 1) * 8);

            #pragma unroll
            for (int mt = 0; mt < 4; ++mt)
                #pragma unroll
                for (int nt = 0; nt < 4; ++nt)
                    mma_tf32(acc[mt][nt],
                             __float_as_uint(a0[mt][0].x), __float_as_uint(a0[mt][1].x),
                             __float_as_uint(a0[mt][0].y), __float_as_uint(a0[mt][1].y),
                             __float_as_uint(b0[nt].x), __float_as_uint(b0[nt].y));

            if (ks + 2 < NK) {
                // prefetch stage 0 <- ks+2
                #pragma unroll
                for (int mt = 0; mt < 4; ++mt) {
                    a0[mt][0] = *(const float2*)(Apt[mt] + (ks + 2) * 8);
                    a0[mt][1] = *(const float2*)(Apt[mt] + (ks + 2) * 8 + 8 * LDPA);
                }
                #pragma unroll
                for (int nt = 0; nt < 4; ++nt)
                    b0[nt] = *(const float2*)(Bpt[nt] + (ks + 2) * 8);
            }

            #pragma unroll
            for (int mt = 0; mt < 4; ++mt)
                #pragma unroll
                for (int nt = 0; nt < 4; ++nt)
                    mma_tf32(acc[mt][nt],
                             __float_as_uint(a1[mt][0].x), __float_as_uint(a1[mt][1].x),
                             __float_as_uint(a1[mt][0].y), __float_as_uint(a1[mt][1].y),
                             __float_as_uint(b1[nt].x), __float_as_uint(b1[nt].y));
        }

        // Write unnormalized tile + accumulate ssq
        #pragma unroll
        for (int mt = 0; mt < 4; ++mt) {
            int r0 = ibase + wm * 64 + mt * 16 + gid;
            #pragma unroll
            for (int nt = 0; nt < 4; ++nt) {
                int c = jt * 128 + wn * 32 + nt * 8 + tg * 2;
                float* p0 = outBO + (size_t)r0 * HS + c;
                float* p1 = outBO + (size_t)(r0 + 8) * HS + c;
                float c0 = acc[mt][nt][0], c1 = acc[mt][nt][1];
                float c2 = acc[mt][nt][2], c3 = acc[mt][nt][3];
                *(float2*)p0 = make_float2(c0, c1);
                *(float2*)p1 = make_float2(c2, c3);
                ssqr[mt][0] += c0 * c0 + c1 * c1;
                ssqr[mt][1] += c2 * c2 + c3 * c3;
            }
        }
    }

    // ssq/scale arrays live in the (now dead) B region
    __syncthreads();
    if (tid < 256) s_ssq[tid] = 0.f;
    __syncthreads();
    #pragma unroll
    for (int mt = 0; mt < 4; ++mt)
        #pragma unroll
        for (int h = 0; h < 2; ++h) {
            float v = ssqr[mt][h];
            v += __shfl_xor_sync(0xffffffffu, v, 1);
            v += __shfl_xor_sync(0xffffffffu, v, 2);
            if (tg == 0)
                atomicAdd(&s_ssq[wm * 64 + mt * 16 + h * 8 + gid], v);
        }
    __syncthreads();
    if (tid < 256)
        s_scale[tid] = 1.f / fmaxf(sqrtf(s_ssq[tid]), 1e-12f);
    __syncthreads();

    // In-place rescale of this CTA's 256x1024 tile (L2-hot re-read)
    for (int l = tid; l < 256 * 256; l += 512) {
        int r = l >> 8, c4 = l & 255;
        float sc = s_scale[r];
        float4* p = (float4*)(outBO + (size_t)(ibase + r) * HS) + c4;
        float4 v = *p;
        v.x *= sc; v.y *= sc; v.z *= sc; v.w *= sc;
        *p = v;
    }
}

// ---------------------------------------------------------------------------
extern "C" void kernel_launch(void* const* d_in, const int* in_sizes, int n_in,
                              void* d_out, int out_size)
{
    const float* x  = (const float*)d_in[0];
    const float* w1 = (const float*)d_in[1];
    const float* b1 = (const float*)d_in[2];
    const float* w2 = (const float*)d_in[3];
    const float* b2 = (const float*)d_in[4];
    float* out = (float*)d_out;

    cudaFuncSetAttribute(big_mma, cudaFuncAttributeMaxDynamicSharedMemorySize, SMEM_MMA);

    dim3 tpb(256);
    proj_kernel<<<dim3(7, 16, Bn), tpb>>>(x, w1, b1, 0);
    proj_kernel<<<dim3(7, 16, Bn), tpb>>>(x, w2, b2, 1);
    gather_kernel<<<Bn * HS + Bn * On * HS, 160>>>();
    big_mma<<<dim3(HS / 256, On, Bn), dim3(512), SMEM_MMA>>>(out);
}

// round 10
// speedup vs baseline: 2.0898x; 1.0371x over previous
#include <cuda_runtime.h>
#include <cstdint>

// Problem constants
#define Bn 8
#define Cc 512
#define Ww 14
#define HS 1024
#define Sp 196      // 14*14
#define KC 144      // 12*12 interior centers
#define On 9        // 3x3 offsets
#define NK 18       // 144 / 8 k-steps

// Scratch (__device__ globals: allocation-free rule)
__device__ float g_P1[Bn * HS * Sp];
__device__ float g_P2[Bn * HS * Sp];
__device__ float g_Ag[(size_t)Bn * HS * KC];          // gathered, tf32-rounded, k-permuted
__device__ float g_Bg[(size_t)Bn * On * HS * KC];     // gathered, tf32-rounded, k-permuted
__device__ float g_G[(size_t)Bn * On * KC * KC];      // Gram matrices (permuted k-space, tf32)
__device__ float g_scale[(size_t)Bn * On * HS];       // per-row 1/max(||row||,eps)

__device__ __forceinline__ void mma_tf32(float* c, uint32_t a0, uint32_t a1,
                                         uint32_t a2, uint32_t a3,
                                         uint32_t b0, uint32_t b1) {
    asm volatile(
        "mma.sync.aligned.m16n8k8.row.col.f32.tf32.tf32.f32 "
        "{%0,%1,%2,%3}, {%4,%5,%6,%7}, {%8,%9}, {%0,%1,%2,%3};"
        : "+f"(c[0]), "+f"(c[1]), "+f"(c[2]), "+f"(c[3])
        : "r"(a0), "r"(a1), "r"(a2), "r"(a3), "r"(b0), "r"(b1));
}

// ---------------------------------------------------------------------------
// proj: P[b][h][s] = sum_c w[h][c] * x[b][c][s] + bias[h]   (unchanged, passing)
// ---------------------------------------------------------------------------
__global__ __launch_bounds__(256) void proj_kernel(const float* __restrict__ x,
                                                   const float* __restrict__ w,
                                                   const float* __restrict__ bias,
                                                   int which)
{
    __shared__ __align__(16) float Wst[32 * 68];
    __shared__ __align__(16) float Xs[32 * 33];

    float* outP = which ? g_P2 : g_P1;
    const int tid = threadIdx.x;
    const int tx = tid & 15;
    const int ty = tid >> 4;
    const int sbase = blockIdx.x * 32;
    const int hbase = blockIdx.y * 64;
    const int b = blockIdx.z;

    float acc[4][2] = {};
    for (int cb = 0; cb < Cc; cb += 32) {
        #pragma unroll
        for (int r = 0; r < 8; ++r) {
            int l = tid + r * 256;
            int h = l >> 5, c = l & 31;
            Wst[c * 68 + h] = w[(hbase + h) * Cc + cb + c];
        }
        #pragma unroll
        for (int r = 0; r < 4; ++r) {
            int l = tid + r * 256;
            int c = l >> 5, s = l & 31;
            int sg = sbase + s;
            Xs[c * 33 + s] = (sg < Sp) ? x[(b * Cc + cb + c) * Sp + sg] : 0.f;
        }
        __syncthreads();
        #pragma unroll 8
        for (int c = 0; c < 32; ++c) {
            float4 a = *(const float4*)(Wst + c * 68 + ty * 4);
            float b0 = Xs[c * 33 + tx * 2];
            float b1 = Xs[c * 33 + tx * 2 + 1];
            acc[0][0] += a.x * b0; acc[0][1] += a.x * b1;
            acc[1][0] += a.y * b0; acc[1][1] += a.y * b1;
            acc[2][0] += a.z * b0; acc[2][1] += a.z * b1;
            acc[3][0] += a.w * b0; acc[3][1] += a.w * b1;
        }
        __syncthreads();
    }
    #pragma unroll
    for (int u = 0; u < 4; ++u) {
        int h = hbase + ty * 4 + u;
        float bb = bias[h];
        #pragma unroll
        for (int v = 0; v < 2; ++v) {
            int s = sbase + tx * 2 + v;
            if (s < Sp) outP[(b * HS + h) * Sp + s] = acc[u][v] + bb;
        }
    }
}

// ---------------------------------------------------------------------------
// gather: gathered operands, tf32-rounded, k-chunk permuted [0,4,1,5,2,6,3,7]
// so the mma fragment pair (k0, k0+4) is a contiguous float2.
// ---------------------------------------------------------------------------
__global__ __launch_bounds__(160) void gather_kernel()
{
    int row = blockIdx.x;
    int k = threadIdx.x;
    if (k >= KC) return;
    int ky = k / 12, kx = k - ky * 12;
    int ks = k >> 3, kk = k & 7;
    int dpos = ks * 8 + (kk & 3) * 2 + (kk >> 2);
    float v;
    if (row < Bn * HS) {
        int s = (1 + ky) * Ww + 1 + kx;
        v = g_P1[(size_t)row * Sp + s];
        asm("cvt.rna.tf32.f32 %0, %0;" : "+f"(v));
        g_Ag[(size_t)row * KC + dpos] = v;
    } else {
        int r2 = row - Bn * HS;
        int b = r2 / (On * HS);
        int rem = r2 - b * On * HS;
        int o = rem >> 10;
        int j = rem & 1023;
        int delta = (o / 3 - 1) * Ww + (o % 3 - 1);
        int s = (1 + ky) * Ww + 1 + kx + delta;
        v = g_P2[((size_t)b * HS + j) * Sp + s];
        asm("cvt.rna.tf32.f32 %0, %0;" : "+f"(v));
        g_Bg[(size_t)r2 * KC + dpos] = v;
    }
}

// ---------------------------------------------------------------------------
// gram: G_o = Bg_o^T Bg_o (144x144, permuted k-space), per (b,o).
// CTA = (o,b), 288 threads = 9 warps (3m x 3n), warp tile 48x48.
// K = 1024 j in 16 chunks of 64, transposed into smem T[k][j] (pitch 65).
// ---------------------------------------------------------------------------
#define TP 65
__global__ __launch_bounds__(288) void gram_kernel()
{
    __shared__ float T[KC * TP];     // 37.4 KB

    const int tid = threadIdx.x;
    const int wid = tid >> 5;
    const int lane = tid & 31;
    const int gid = lane >> 2;
    const int tg = lane & 3;
    const int wm = wid / 3;
    const int wn = wid % 3;
    const int o = blockIdx.x;
    const int b = blockIdx.y;

    const float* Bb = g_Bg + ((size_t)(b * On + o) * HS) * KC;
    float acc[3][6][4] = {};

    for (int jc = 0; jc < 16; ++jc) {
        __syncthreads();
        // load 64 rows x 144 k, transpose into T[k][j]
        for (int l = tid; l < 64 * 36; l += 288) {
            int j = l / 36, k4 = l - j * 36;
            float4 v = *(const float4*)(Bb + (size_t)(jc * 64 + j) * KC + k4 * 4);
            T[(4 * k4 + 0) * TP + j] = v.x;
            T[(4 * k4 + 1) * TP + j] = v.y;
            T[(4 * k4 + 2) * TP + j] = v.z;
            T[(4 * k4 + 3) * TP + j] = v.w;
        }
        __syncthreads();

        #pragma unroll
        for (int js = 0; js < 8; ++js) {
            int j0 = js * 8 + tg;
            uint32_t af[3][4], bf[6][2];
            #pragma unroll
            for (int mt = 0; mt < 3; ++mt) {
                int m = wm * 48 + mt * 16 + gid;
                af[mt][0] = __float_as_uint(T[m * TP + j0]);
                af[mt][1] = __float_as_uint(T[(m + 8) * TP + j0]);
                af[mt][2] = __float_as_uint(T[m * TP + j0 + 4]);
                af[mt][3] = __float_as_uint(T[(m + 8) * TP + j0 + 4]);
            }
            #pragma unroll
            for (int nt = 0; nt < 6; ++nt) {
                int n = wn * 48 + nt * 8 + gid;
                bf[nt][0] = __float_as_uint(T[n * TP + j0]);
                bf[nt][1] = __float_as_uint(T[n * TP + j0 + 4]);
            }
            #pragma unroll
            for (int mt = 0; mt < 3; ++mt)
                #pragma unroll
                for (int nt = 0; nt < 6; ++nt)
                    mma_tf32(acc[mt][nt], af[mt][0], af[mt][1], af[mt][2], af[mt][3],
                             bf[nt][0], bf[nt][1]);
        }
    }

    // write G (tf32-rounded, since qform feeds it back into mma)
    float* Gp = g_G + (size_t)(b * On + o) * KC * KC;
    #pragma unroll
    for (int mt = 0; mt < 3; ++mt) {
        int r = wm * 48 + mt * 16 + gid;
        #pragma unroll
        for (int nt = 0; nt < 6; ++nt) {
            int c = wn * 48 + nt * 8 + tg * 2;
            float c0 = acc[mt][nt][0], c1 = acc[mt][nt][1];
            float c2 = acc[mt][nt][2], c3 = acc[mt][nt][3];
            asm("cvt.rna.tf32.f32 %0, %0;" : "+f"(c0));
            asm("cvt.rna.tf32.f32 %0, %0;" : "+f"(c1));
            asm("cvt.rna.tf32.f32 %0, %0;" : "+f"(c2));
            asm("cvt.rna.tf32.f32 %0, %0;" : "+f"(c3));
            *(float2*)(Gp + r * KC + c) = make_float2(c0, c1);
            *(float2*)(Gp + (r + 8) * KC + c) = make_float2(c2, c3);
        }
    }
}

// ---------------------------------------------------------------------------
// qform: ssq[b,o,i] = a_i^T G_o a_i via C = A*G (CTA-local), then rowdot(A,C).
// CTA = (i-tile 128, o, b), 256 threads = 8 warps (4m x 2n), warp tile 32x72.
// Writes g_scale = 1/max(sqrt(ssq), eps). Q never touches DRAM.
// ---------------------------------------------------------------------------
#define QP 148
#define QA_OFF 512
#define QG_OFF (QA_OFF + 128 * QP * 4)
#define SMEM_QF (QG_OFF + KC * QP * 4)     // 512 + 75776 + 85248 = 161536

__global__ __launch_bounds__(256, 1) void qform_kernel()
{
    extern __shared__ __align__(16) char smq[];
    float* s_q = (float*)smq;                 // [128]
    float* As = (float*)(smq + QA_OFF);
    float* Gs = (float*)(smq + QG_OFF);

    const int tid = threadIdx.x;
    const int wid = tid >> 5;
    const int lane = tid & 31;
    const int gid = lane >> 2;
    const int tg = lane & 3;
    const int wm = wid & 3;                   // 4 m-bands of 32
    const int wn = wid >> 2;                  // 2 n-bands of 72
    const int ibase = blockIdx.x * 128;
    const int o = blockIdx.y;
    const int b = blockIdx.z;

    const float* Ab = g_Ag + ((size_t)b * HS + ibase) * KC;
    const float* Gp = g_G + (size_t)(b * On + o) * KC * KC;

    if (tid < 128) s_q[tid] = 0.f;
    for (int l = tid; l < 128 * 36; l += 256) {
        int r = l / 36, k4 = l - r * 36;
        *(float4*)(As + r * QP + k4 * 4) = *(const float4*)(Ab + (size_t)r * KC + k4 * 4);
    }
    for (int l = tid; l < KC * 36; l += 256) {
        int r = l / 36, k4 = l - r * 36;
        *(float4*)(Gs + r * QP + k4 * 4) = *(const float4*)(Gp + (size_t)r * KC + k4 * 4);
    }
    __syncthreads();

    float acc[2][9][4] = {};
    #pragma unroll
    for (int ks = 0; ks < NK; ++ks) {
        int kp = ks * 8 + tg * 2;             // permuted layout: (k0,k0+4) contiguous
        float2 af[2][2];
        #pragma unroll
        for (int mt = 0; mt < 2; ++mt) {
            int r = wm * 32 + mt * 16 + gid;
            af[mt][0] = *(const float2*)(As + r * QP + kp);
            af[mt][1] = *(const float2*)(As + (r + 8) * QP + kp);
        }
        #pragma unroll
        for (int nt = 0; nt < 9; ++nt) {
            int n = wn * 72 + nt * 8 + gid;
            float2 bv = *(const float2*)(Gs + n * QP + kp);
            #pragma unroll
            for (int mt = 0; mt < 2; ++mt)
                mma_tf32(acc[mt][nt],
                         __float_as_uint(af[mt][0].x), __float_as_uint(af[mt][1].x),
                         __float_as_uint(af[mt][0].y), __float_as_uint(af[mt][1].y),
                         __float_as_uint(bv.x), __float_as_uint(bv.y));
        }
    }

    // rowdot with A, reduce over tg lanes, then smem atomics across wn
    #pragma unroll
    for (int mt = 0; mt < 2; ++mt) {
        int r = wm * 32 + mt * 16 + gid;
        float lo = 0.f, hi = 0.f;
        #pragma unroll
        for (int nt = 0; nt < 9; ++nt) {
            int c = wn * 72 + nt * 8 + tg * 2;
            lo += acc[mt][nt][0] * As[r * QP + c] + acc[mt][nt][1] * As[r * QP + c + 1];
            hi += acc[mt][nt][2] * As[(r + 8) * QP + c] + acc[mt][nt][3] * As[(r + 8) * QP + c + 1];
        }
        lo += __shfl_xor_sync(0xffffffffu, lo, 1);
        lo += __shfl_xor_sync(0xffffffffu, lo, 2);
        hi += __shfl_xor_sync(0xffffffffu, hi, 1);
        hi += __shfl_xor_sync(0xffffffffu, hi, 2);
        if (tg == 0) {
            atomicAdd(&s_q[r], lo);
            atomicAdd(&s_q[r + 8], hi);
        }
    }
    __syncthreads();
    if (tid < 128)
        g_scale[(size_t)(b * On + o) * HS + ibase + tid] =
            1.f / fmaxf(sqrtf(s_q[tid]), 1e-12f);
}

// ---------------------------------------------------------------------------
// big_mma: cofe GEMM via mma.sync m16n8k8 tf32, single pass, pre-scaled write.
// CTA = (i-tile 256, o, b), 512 threads = 16 warps (4m x 4n), warp tile 64x32.
// ---------------------------------------------------------------------------
#define LDPA 152
#define LDPB 148
#define A_OFF 0
#define B_OFF (256 * LDPA * 4)                  // 155648
#define SMEM_MMA (B_OFF + 128 * LDPB * 4)       // 231424

__global__ __launch_bounds__(512, 1) void big_mma(float* __restrict__ out)
{
    extern __shared__ __align__(16) char sm[];
    float* As = (float*)(sm + A_OFF);
    float* Bs = (float*)(sm + B_OFF);

    const int tid = threadIdx.x;
    const int wid = tid >> 5;
    const int lane = tid & 31;
    const int gid = lane >> 2;
    const int tg = lane & 3;
    const int wm = wid & 3;
    const int wn = wid >> 2;

    const int ibase = blockIdx.x * 256;
    const int o = blockIdx.y;
    const int b = blockIdx.z;

    const float* Ab = g_Ag + ((size_t)b * HS + ibase) * KC;
    const float* Bb = g_Bg + ((size_t)(b * On + o) * HS) * KC;
    float* outBO = out + (size_t)(b * On + o) * HS * HS;

    // per-thread row scales (8 rows/thread)
    float sc[4][2];
    {
        const float* scp = g_scale + (size_t)(b * On + o) * HS + ibase;
        #pragma unroll
        for (int mt = 0; mt < 4; ++mt) {
            int r = wm * 64 + mt * 16 + gid;
            sc[mt][0] = scp[r];
            sc[mt][1] = scp[r + 8];
        }
    }

    // Load A tile
    for (int l = tid; l < 256 * 36; l += 512) {
        int r = l / 36, k4 = l - r * 36;
        *(float4*)(As + r * LDPA + k4 * 4) = *(const float4*)(Ab + (size_t)r * KC + k4 * 4);
    }

    const float* Apt[4];
    const float* Bpt[4];
    #pragma unroll
    for (int mt = 0; mt < 4; ++mt)
        Apt[mt] = As + (wm * 64 + mt * 16 + gid) * LDPA + tg * 2;
    #pragma unroll
    for (int nt = 0; nt < 4; ++nt)
        Bpt[nt] = Bs + (wn * 32 + nt * 8 + gid) * LDPB + tg * 2;

    #pragma unroll 1
    for (int jt = 0; jt < 8; ++jt) {
        __syncthreads();
        const float* Bt = Bb + (size_t)(jt * 128) * KC;
        for (int l = tid; l < 128 * 36; l += 512) {
            int r = l / 36, k4 = l - r * 36;
            *(float4*)(Bs + r * LDPB + k4 * 4) = *(const float4*)(Bt + (size_t)r * KC + k4 * 4);
        }
        __syncthreads();

        float acc[4][4][4] = {};
        float2 a0[4][2], a1[4][2], b0[4], b1[4];

        #pragma unroll
        for (int mt = 0; mt < 4; ++mt) {
            a0[mt][0] = *(const float2*)(Apt[mt]);
            a0[mt][1] = *(const float2*)(Apt[mt] + 8 * LDPA);
        }
        #pragma unroll
        for (int nt = 0; nt < 4; ++nt)
            b0[nt] = *(const float2*)(Bpt[nt]);

        #pragma unroll
        for (int ks = 0; ks < NK; ks += 2) {
            #pragma unroll
            for (int mt = 0; mt < 4; ++mt) {
                a1[mt][0] = *(const float2*)(Apt[mt] + (ks + 1) * 8);
                a1[mt][1] = *(const float2*)(Apt[mt] + (ks + 1) * 8 + 8 * LDPA);
            }
            #pragma unroll
            for (int nt = 0; nt < 4; ++nt)
                b1[nt] = *(const float2*)(Bpt[nt] + (ks + 1) * 8);

            #pragma unroll
            for (int mt = 0; mt < 4; ++mt)
                #pragma unroll
                for (int nt = 0; nt < 4; ++nt)
                    mma_tf32(acc[mt][nt],
                             __float_as_uint(a0[mt][0].x), __float_as_uint(a0[mt][1].x),
                             __float_as_uint(a0[mt][0].y), __float_as_uint(a0[mt][1].y),
                             __float_as_uint(b0[nt].x), __float_as_uint(b0[nt].y));

            if (ks + 2 < NK) {
                #pragma unroll
                for (int mt = 0; mt < 4; ++mt) {
                    a0[mt][0] = *(const float2*)(Apt[mt] + (ks + 2) * 8);
                    a0[mt][1] = *(const float2*)(Apt[mt] + (ks + 2) * 8 + 8 * LDPA);
                }
                #pragma unroll
                for (int nt = 0; nt < 4; ++nt)
                    b0[nt] = *(const float2*)(Bpt[nt] + (ks + 2) * 8);
            }

            #pragma unroll
            for (int mt = 0; mt < 4; ++mt)
                #pragma unroll
                for (int nt = 0; nt < 4; ++nt)
                    mma_tf32(acc[mt][nt],
                             __float_as_uint(a1[mt][0].x), __float_as_uint(a1[mt][1].x),
                             __float_as_uint(a1[mt][0].y), __float_as_uint(a1[mt][1].y),
                             __float_as_uint(b1[nt].x), __float_as_uint(b1[nt].y));
        }

        // Write scaled output (single pass, no rescale round-trip)
        #pragma unroll
        for (int mt = 0; mt < 4; ++mt) {
            int r0 = ibase + wm * 64 + mt * 16 + gid;
            float s0 = sc[mt][0], s1 = sc[mt][1];
            #pragma unroll
            for (int nt = 0; nt < 4; ++nt) {
                int c = jt * 128 + wn * 32 + nt * 8 + tg * 2;
                *(float2*)(outBO + (size_t)r0 * HS + c) =
                    make_float2(acc[mt][nt][0] * s0, acc[mt][nt][1] * s0);
                *(float2*)(outBO + (size_t)(r0 + 8) * HS + c) =
                    make_float2(acc[mt][nt][2] * s1, acc[mt][nt][3] * s1);
            }
        }
    }
}

// ---------------------------------------------------------------------------
extern "C" void kernel_launch(void* const* d_in, const int* in_sizes, int n_in,
                              void* d_out, int out_size)
{
    const float* x  = (const float*)d_in[0];
    const float* w1 = (const float*)d_in[1];
    const float* b1 = (const float*)d_in[2];
    const float* w2 = (const float*)d_in[3];
    const float* b2 = (const float*)d_in[4];
    float* out = (float*)d_out;

    cudaFuncSetAttribute(big_mma, cudaFuncAttributeMaxDynamicSharedMemorySize, SMEM_MMA);
    cudaFuncSetAttribute(qform_kernel, cudaFuncAttributeMaxDynamicSharedMemorySize, SMEM_QF);

    dim3 tpb(256);
    proj_kernel<<<dim3(7, 16, Bn), tpb>>>(x, w1, b1, 0);
    proj_kernel<<<dim3(7, 16, Bn), tpb>>>(x, w2, b2, 1);
    gather_kernel<<<Bn * HS + Bn * On * HS, 160>>>();
    gram_kernel<<<dim3(On, Bn), 288>>>();
    qform_kernel<<<dim3(8, On, Bn), 256, SMEM_QF>>>();
    big_mma<<<dim3(HS / 256, On, Bn), dim3(512), SMEM_MMA>>>(out);
}

// round 11
// speedup vs baseline: 2.2599x; 1.0814x over previous
#include <cuda_runtime.h>
#include <cstdint>

// Problem constants
#define Bn 8
#define Cc 512
#define Ww 14
#define HS 1024
#define Sp 196      // 14*14
#define KC 144      // 12*12 interior centers
#define On 9        // 3x3 offsets
#define NK 18       // 144 / 8 k-steps

// Scratch (__device__ globals: allocation-free rule)
__device__ float g_P1[Bn * HS * Sp];
__device__ float g_P2[Bn * HS * Sp];
__device__ float g_Ag[(size_t)Bn * HS * KC];          // gathered, tf32-rounded, k-permuted
__device__ float g_Bg[(size_t)Bn * On * HS * KC];     // gathered, tf32-rounded, k-permuted
__device__ float g_Gp[2 * (size_t)Bn * On * KC * KC]; // partial Gram matrices (2 j-halves)
__device__ float g_scale[(size_t)Bn * On * HS];       // per-row 1/max(||row||,eps)

__device__ __forceinline__ void mma_tf32(float* c, uint32_t a0, uint32_t a1,
                                         uint32_t a2, uint32_t a3,
                                         uint32_t b0, uint32_t b1) {
    asm volatile(
        "mma.sync.aligned.m16n8k8.row.col.f32.tf32.tf32.f32 "
        "{%0,%1,%2,%3}, {%4,%5,%6,%7}, {%8,%9}, {%0,%1,%2,%3};"
        : "+f"(c[0]), "+f"(c[1]), "+f"(c[2]), "+f"(c[3])
        : "r"(a0), "r"(a1), "r"(a2), "r"(a3), "r"(b0), "r"(b1));
}

// ---------------------------------------------------------------------------
// proj: P[b][h][s] = sum_c w[h][c] * x[b][c][s] + bias[h]   (unchanged, passing)
// ---------------------------------------------------------------------------
__global__ __launch_bounds__(256) void proj_kernel(const float* __restrict__ x,
                                                   const float* __restrict__ w,
                                                   const float* __restrict__ bias,
                                                   int which)
{
    __shared__ __align__(16) float Wst[32 * 68];
    __shared__ __align__(16) float Xs[32 * 33];

    float* outP = which ? g_P2 : g_P1;
    const int tid = threadIdx.x;
    const int tx = tid & 15;
    const int ty = tid >> 4;
    const int sbase = blockIdx.x * 32;
    const int hbase = blockIdx.y * 64;
    const int b = blockIdx.z;

    float acc[4][2] = {};
    for (int cb = 0; cb < Cc; cb += 32) {
        #pragma unroll
        for (int r = 0; r < 8; ++r) {
            int l = tid + r * 256;
            int h = l >> 5, c = l & 31;
            Wst[c * 68 + h] = w[(hbase + h) * Cc + cb + c];
        }
        #pragma unroll
        for (int r = 0; r < 4; ++r) {
            int l = tid + r * 256;
            int c = l >> 5, s = l & 31;
            int sg = sbase + s;
            Xs[c * 33 + s] = (sg < Sp) ? x[(b * Cc + cb + c) * Sp + sg] : 0.f;
        }
        __syncthreads();
        #pragma unroll 8
        for (int c = 0; c < 32; ++c) {
            float4 a = *(const float4*)(Wst + c * 68 + ty * 4);
            float b0 = Xs[c * 33 + tx * 2];
            float b1 = Xs[c * 33 + tx * 2 + 1];
            acc[0][0] += a.x * b0; acc[0][1] += a.x * b1;
            acc[1][0] += a.y * b0; acc[1][1] += a.y * b1;
            acc[2][0] += a.z * b0; acc[2][1] += a.z * b1;
            acc[3][0] += a.w * b0; acc[3][1] += a.w * b1;
        }
        __syncthreads();
    }
    #pragma unroll
    for (int u = 0; u < 4; ++u) {
        int h = hbase + ty * 4 + u;
        float bb = bias[h];
        #pragma unroll
        for (int v = 0; v < 2; ++v) {
            int s = sbase + tx * 2 + v;
            if (s < Sp) outP[(b * HS + h) * Sp + s] = acc[u][v] + bb;
        }
    }
}

// ---------------------------------------------------------------------------
// gather: gathered operands, tf32-rounded, k-chunk permuted [0,4,1,5,2,6,3,7]
// so the mma fragment pair (k0, k0+4) is a contiguous float2.
// ---------------------------------------------------------------------------
__global__ __launch_bounds__(160) void gather_kernel()
{
    int row = blockIdx.x;
    int k = threadIdx.x;
    if (k >= KC) return;
    int ky = k / 12, kx = k - ky * 12;
    int ks = k >> 3, kk = k & 7;
    int dpos = ks * 8 + (kk & 3) * 2 + (kk >> 2);
    float v;
    if (row < Bn * HS) {
        int s = (1 + ky) * Ww + 1 + kx;
        v = g_P1[(size_t)row * Sp + s];
        asm("cvt.rna.tf32.f32 %0, %0;" : "+f"(v));
        g_Ag[(size_t)row * KC + dpos] = v;
    } else {
        int r2 = row - Bn * HS;
        int b = r2 / (On * HS);
        int rem = r2 - b * On * HS;
        int o = rem >> 10;
        int j = rem & 1023;
        int delta = (o / 3 - 1) * Ww + (o % 3 - 1);
        int s = (1 + ky) * Ww + 1 + kx + delta;
        v = g_P2[((size_t)b * HS + j) * Sp + s];
        asm("cvt.rna.tf32.f32 %0, %0;" : "+f"(v));
        g_Bg[(size_t)r2 * KC + dpos] = v;
    }
}

// ---------------------------------------------------------------------------
// gram: partial Gram G_half = Bg_half^T Bg_half (144x144), per (b,o,half).
// CTA = (o, b, half), 288 threads = 9 warps (3m x 3n), warp tile 48x48.
// Each half covers 512 j in 8 chunks of 64, DOUBLE-BUFFERED: LDG of chunk c+1
// overlaps the MMAs of chunk c. Output: raw fp32 partial (qform sums+rounds).
// ---------------------------------------------------------------------------
#define TP 65
#define TBUF (KC * TP)
#define SMEM_GRAM (2 * TBUF * 4)   // 74880

__global__ __launch_bounds__(288, 1) void gram_kernel()
{
    extern __shared__ __align__(16) float T[];   // [2][KC*TP]

    const int tid = threadIdx.x;
    const int wid = tid >> 5;
    const int lane = tid & 31;
    const int gid = lane >> 2;
    const int tg = lane & 3;
    const int wm = wid / 3;
    const int wn = wid % 3;
    const int o = blockIdx.x;
    const int b = blockIdx.y;
    const int half = blockIdx.z;

    const float* Bb = g_Bg + ((size_t)(b * On + o) * HS + half * 512) * KC;

    // per-thread load slots: 8 float4 covering 64 rows x 36 float4
    int lj[8], lk4[8];
    #pragma unroll
    for (int r = 0; r < 8; ++r) {
        int l = tid + r * 288;
        lj[r] = l / 36;
        lk4[r] = l - lj[r] * 36;
    }

    float4 ld[8];
    // prologue: LDG chunk 0
    #pragma unroll
    for (int r = 0; r < 8; ++r)
        ld[r] = *(const float4*)(Bb + (size_t)lj[r] * KC + lk4[r] * 4);
    // STS chunk 0 -> buffer 0 (transposed)
    #pragma unroll
    for (int r = 0; r < 8; ++r) {
        float* Tb = T;
        T[(4 * lk4[r] + 0) * TP + lj[r]] = ld[r].x;
        T[(4 * lk4[r] + 1) * TP + lj[r]] = ld[r].y;
        T[(4 * lk4[r] + 2) * TP + lj[r]] = ld[r].z;
        T[(4 * lk4[r] + 3) * TP + lj[r]] = ld[r].w;
        (void)Tb;
    }
    __syncthreads();

    float acc[3][6][4] = {};

    for (int jc = 0; jc < 8; ++jc) {
        const float* cur = T + (jc & 1) * TBUF;
        float* nxt = T + ((jc & 1) ^ 1) * TBUF;

        // prefetch LDG for next chunk (overlaps the MMAs below)
        if (jc < 7) {
            const float* Bc = Bb + (size_t)(jc + 1) * 64 * KC;
            #pragma unroll
            for (int r = 0; r < 8; ++r)
                ld[r] = *(const float4*)(Bc + (size_t)lj[r] * KC + lk4[r] * 4);
        }

        #pragma unroll
        for (int js = 0; js < 8; ++js) {
            int j0 = js * 8 + tg;
            uint32_t af[3][4], bf[6][2];
            #pragma unroll
            for (int mt = 0; mt < 3; ++mt) {
                int m = wm * 48 + mt * 16 + gid;
                af[mt][0] = __float_as_uint(cur[m * TP + j0]);
                af[mt][1] = __float_as_uint(cur[(m + 8) * TP + j0]);
                af[mt][2] = __float_as_uint(cur[m * TP + j0 + 4]);
                af[mt][3] = __float_as_uint(cur[(m + 8) * TP + j0 + 4]);
            }
            #pragma unroll
            for (int nt = 0; nt < 6; ++nt) {
                int n = wn * 48 + nt * 8 + gid;
                bf[nt][0] = __float_as_uint(cur[n * TP + j0]);
                bf[nt][1] = __float_as_uint(cur[n * TP + j0 + 4]);
            }
            #pragma unroll
            for (int mt = 0; mt < 3; ++mt)
                #pragma unroll
                for (int nt = 0; nt < 6; ++nt)
                    mma_tf32(acc[mt][nt], af[mt][0], af[mt][1], af[mt][2], af[mt][3],
                             bf[nt][0], bf[nt][1]);
        }

        // STS next chunk into the other buffer
        if (jc < 7) {
            #pragma unroll
            for (int r = 0; r < 8; ++r) {
                nxt[(4 * lk4[r] + 0) * TP + lj[r]] = ld[r].x;
                nxt[(4 * lk4[r] + 1) * TP + lj[r]] = ld[r].y;
                nxt[(4 * lk4[r] + 2) * TP + lj[r]] = ld[r].z;
                nxt[(4 * lk4[r] + 3) * TP + lj[r]] = ld[r].w;
            }
        }
        __syncthreads();
    }

    // write raw fp32 partial Gram for this half
    float* Gp = g_Gp + ((size_t)half * Bn * On + (size_t)(b * On + o)) * KC * KC;
    #pragma unroll
    for (int mt = 0; mt < 3; ++mt) {
        int r = wm * 48 + mt * 16 + gid;
        #pragma unroll
        for (int nt = 0; nt < 6; ++nt) {
            int c = wn * 48 + nt * 8 + tg * 2;
            *(float2*)(Gp + r * KC + c) = make_float2(acc[mt][nt][0], acc[mt][nt][1]);
            *(float2*)(Gp + (r + 8) * KC + c) = make_float2(acc[mt][nt][2], acc[mt][nt][3]);
        }
    }
}

// ---------------------------------------------------------------------------
// qform: ssq[b,o,i] = a_i^T G_o a_i via C = A*G (CTA-local), then rowdot(A,C).
// G = rna(Gp[0] + Gp[1]) summed at load time. Writes g_scale = 1/max(||.||,eps).
// CTA = (i-tile 128, o, b), 256 threads = 8 warps (4m x 2n), warp tile 32x72.
// ---------------------------------------------------------------------------
#define QP 148
#define QA_OFF 512
#define QG_OFF (QA_OFF + 128 * QP * 4)
#define SMEM_QF (QG_OFF + KC * QP * 4)     // 512 + 75776 + 85248 = 161536

__global__ __launch_bounds__(256, 1) void qform_kernel()
{
    extern __shared__ __align__(16) char smq[];
    float* s_q = (float*)smq;                 // [128]
    float* As = (float*)(smq + QA_OFF);
    float* Gs = (float*)(smq + QG_OFF);

    const int tid = threadIdx.x;
    const int wid = tid >> 5;
    const int lane = tid & 31;
    const int gid = lane >> 2;
    const int tg = lane & 3;
    const int wm = wid & 3;                   // 4 m-bands of 32
    const int wn = wid >> 2;                  // 2 n-bands of 72
    const int ibase = blockIdx.x * 128;
    const int o = blockIdx.y;
    const int b = blockIdx.z;

    const float* Ab = g_Ag + ((size_t)b * HS + ibase) * KC;
    const float* Gp0 = g_Gp + (size_t)(b * On + o) * KC * KC;
    const float* Gp1 = Gp0 + (size_t)Bn * On * KC * KC;

    if (tid < 128) s_q[tid] = 0.f;
    for (int l = tid; l < 128 * 36; l += 256) {
        int r = l / 36, k4 = l - r * 36;
        *(float4*)(As + r * QP + k4 * 4) = *(const float4*)(Ab + (size_t)r * KC + k4 * 4);
    }
    for (int l = tid; l < KC * 36; l += 256) {
        int r = l / 36, k4 = l - r * 36;
        size_t off = (size_t)r * KC + k4 * 4;
        float4 v0 = *(const float4*)(Gp0 + off);
        float4 v1 = *(const float4*)(Gp1 + off);
        float4 v = make_float4(v0.x + v1.x, v0.y + v1.y, v0.z + v1.z, v0.w + v1.w);
        asm("cvt.rna.tf32.f32 %0, %0;" : "+f"(v.x));
        asm("cvt.rna.tf32.f32 %0, %0;" : "+f"(v.y));
        asm("cvt.rna.tf32.f32 %0, %0;" : "+f"(v.z));
        asm("cvt.rna.tf32.f32 %0, %0;" : "+f"(v.w));
        *(float4*)(Gs + r * QP + k4 * 4) = v;
    }
    __syncthreads();

    float acc[2][9][4] = {};
    #pragma unroll
    for (int ks = 0; ks < NK; ++ks) {
        int kp = ks * 8 + tg * 2;             // permuted layout: (k0,k0+4) contiguous
        float2 af[2][2];
        #pragma unroll
        for (int mt = 0; mt < 2; ++mt) {
            int r = wm * 32 + mt * 16 + gid;
            af[mt][0] = *(const float2*)(As + r * QP + kp);
            af[mt][1] = *(const float2*)(As + (r + 8) * QP + kp);
        }
        #pragma unroll
        for (int nt = 0; nt < 9; ++nt) {
            int n = wn * 72 + nt * 8 + gid;
            float2 bv = *(const float2*)(Gs + n * QP + kp);
            #pragma unroll
            for (int mt = 0; mt < 2; ++mt)
                mma_tf32(acc[mt][nt],
                         __float_as_uint(af[mt][0].x), __float_as_uint(af[mt][1].x),
                         __float_as_uint(af[mt][0].y), __float_as_uint(af[mt][1].y),
                         __float_as_uint(bv.x), __float_as_uint(bv.y));
        }
    }

    // rowdot with A, reduce over tg lanes, then smem atomics across wn
    #pragma unroll
    for (int mt = 0; mt < 2; ++mt) {
        int r = wm * 32 + mt * 16 + gid;
        float lo = 0.f, hi = 0.f;
        #pragma unroll
        for (int nt = 0; nt < 9; ++nt) {
            int c = wn * 72 + nt * 8 + tg * 2;
            lo += acc[mt][nt][0] * As[r * QP + c] + acc[mt][nt][1] * As[r * QP + c + 1];
            hi += acc[mt][nt][2] * As[(r + 8) * QP + c] + acc[mt][nt][3] * As[(r + 8) * QP + c + 1];
        }
        lo += __shfl_xor_sync(0xffffffffu, lo, 1);
        lo += __shfl_xor_sync(0xffffffffu, lo, 2);
        hi += __shfl_xor_sync(0xffffffffu, hi, 1);
        hi += __shfl_xor_sync(0xffffffffu, hi, 2);
        if (tg == 0) {
            atomicAdd(&s_q[r], lo);
            atomicAdd(&s_q[r + 8], hi);
        }
    }
    __syncthreads();
    if (tid < 128)
        g_scale[(size_t)(b * On + o) * HS + ibase + tid] =
            1.f / fmaxf(sqrtf(s_q[tid]), 1e-12f);
}

// ---------------------------------------------------------------------------
// big_mma: cofe GEMM via mma.sync m16n8k8 tf32, single pass, pre-scaled write.
// CTA = (i-tile 256, o, b), 512 threads = 16 warps (4m x 4n), warp tile 64x32.
// ---------------------------------------------------------------------------
#define LDPA 152
#define LDPB 148
#define A_OFF 0
#define B_OFF (256 * LDPA * 4)                  // 155648
#define SMEM_MMA (B_OFF + 128 * LDPB * 4)       // 231424

__global__ __launch_bounds__(512, 1) void big_mma(float* __restrict__ out)
{
    extern __shared__ __align__(16) char sm[];
    float* As = (float*)(sm + A_OFF);
    float* Bs = (float*)(sm + B_OFF);

    const int tid = threadIdx.x;
    const int wid = tid >> 5;
    const int lane = tid & 31;
    const int gid = lane >> 2;
    const int tg = lane & 3;
    const int wm = wid & 3;
    const int wn = wid >> 2;

    const int ibase = blockIdx.x * 256;
    const int o = blockIdx.y;
    const int b = blockIdx.z;

    const float* Ab = g_Ag + ((size_t)b * HS + ibase) * KC;
    const float* Bb = g_Bg + ((size_t)(b * On + o) * HS) * KC;
    float* outBO = out + (size_t)(b * On + o) * HS * HS;

    // per-thread row scales (8 rows/thread)
    float sc[4][2];
    {
        const float* scp = g_scale + (size_t)(b * On + o) * HS + ibase;
        #pragma unroll
        for (int mt = 0; mt < 4; ++mt) {
            int r = wm * 64 + mt * 16 + gid;
            sc[mt][0] = scp[r];
            sc[mt][1] = scp[r + 8];
        }
    }

    // Load A tile
    for (int l = tid; l < 256 * 36; l += 512) {
        int r = l / 36, k4 = l - r * 36;
        *(float4*)(As + r * LDPA + k4 * 4) = *(const float4*)(Ab + (size_t)r * KC + k4 * 4);
    }

    const float* Apt[4];
    const float* Bpt[4];
    #pragma unroll
    for (int mt = 0; mt < 4; ++mt)
        Apt[mt] = As + (wm * 64 + mt * 16 + gid) * LDPA + tg * 2;
    #pragma unroll
    for (int nt = 0; nt < 4; ++nt)
        Bpt[nt] = Bs + (wn * 32 + nt * 8 + gid) * LDPB + tg * 2;

    #pragma unroll 1
    for (int jt = 0; jt < 8; ++jt) {
        __syncthreads();
        const float* Bt = Bb + (size_t)(jt * 128) * KC;
        for (int l = tid; l < 128 * 36; l += 512) {
            int r = l / 36, k4 = l - r * 36;
            *(float4*)(Bs + r * LDPB + k4 * 4) = *(const float4*)(Bt + (size_t)r * KC + k4 * 4);
        }
        __syncthreads();

        float acc[4][4][4] = {};
        float2 a0[4][2], a1[4][2], b0[4], b1[4];

        #pragma unroll
        for (int mt = 0; mt < 4; ++mt) {
            a0[mt][0] = *(const float2*)(Apt[mt]);
            a0[mt][1] = *(const float2*)(Apt[mt] + 8 * LDPA);
        }
        #pragma unroll
        for (int nt = 0; nt < 4; ++nt)
            b0[nt] = *(const float2*)(Bpt[nt]);

        #pragma unroll
        for (int ks = 0; ks < NK; ks += 2) {
            #pragma unroll
            for (int mt = 0; mt < 4; ++mt) {
                a1[mt][0] = *(const float2*)(Apt[mt] + (ks + 1) * 8);
                a1[mt][1] = *(const float2*)(Apt[mt] + (ks + 1) * 8 + 8 * LDPA);
            }
            #pragma unroll
            for (int nt = 0; nt < 4; ++nt)
                b1[nt] = *(const float2*)(Bpt[nt] + (ks + 1) * 8);

            #pragma unroll
            for (int mt = 0; mt < 4; ++mt)
                #pragma unroll
                for (int nt = 0; nt < 4; ++nt)
                    mma_tf32(acc[mt][nt],
                             __float_as_uint(a0[mt][0].x), __float_as_uint(a0[mt][1].x),
                             __float_as_uint(a0[mt][0].y), __float_as_uint(a0[mt][1].y),
                             __float_as_uint(b0[nt].x), __float_as_uint(b0[nt].y));

            if (ks + 2 < NK) {
                #pragma unroll
                for (int mt = 0; mt < 4; ++mt) {
                    a0[mt][0] = *(const float2*)(Apt[mt] + (ks + 2) * 8);
                    a0[mt][1] = *(const float2*)(Apt[mt] + (ks + 2) * 8 + 8 * LDPA);
                }
                #pragma unroll
                for (int nt = 0; nt < 4; ++nt)
                    b0[nt] = *(const float2*)(Bpt[nt] + (ks + 2) * 8);
            }

            #pragma unroll
            for (int mt = 0; mt < 4; ++mt)
                #pragma unroll
                for (int nt = 0; nt < 4; ++nt)
                    mma_tf32(acc[mt][nt],
                             __float_as_uint(a1[mt][0].x), __float_as_uint(a1[mt][1].x),
                             __float_as_uint(a1[mt][0].y), __float_as_uint(a1[mt][1].y),
                             __float_as_uint(b1[nt].x), __float_as_uint(b1[nt].y));
        }

        // Write scaled output (single pass, no rescale round-trip)
        #pragma unroll
        for (int mt = 0; mt < 4; ++mt) {
            int r0 = ibase + wm * 64 + mt * 16 + gid;
            float s0 = sc[mt][0], s1 = sc[mt][1];
            #pragma unroll
            for (int nt = 0; nt < 4; ++nt) {
                int c = jt * 128 + wn * 32 + nt * 8 + tg * 2;
                *(float2*)(outBO + (size_t)r0 * HS + c) =
                    make_float2(acc[mt][nt][0] * s0, acc[mt][nt][1] * s0);
                *(float2*)(outBO + (size_t)(r0 + 8) * HS + c) =
                    make_float2(acc[mt][nt][2] * s1, acc[mt][nt][3] * s1);
            }
        }
    }
}

// ---------------------------------------------------------------------------
extern "C" void kernel_launch(void* const* d_in, const int* in_sizes, int n_in,
                              void* d_out, int out_size)
{
    const float* x  = (const float*)d_in[0];
    const float* w1 = (const float*)d_in[1];
    const float* b1 = (const float*)d_in[2];
    const float* w2 = (const float*)d_in[3];
    const float* b2 = (const float*)d_in[4];
    float* out = (float*)d_out;

    cudaFuncSetAttribute(big_mma, cudaFuncAttributeMaxDynamicSharedMemorySize, SMEM_MMA);
    cudaFuncSetAttribute(qform_kernel, cudaFuncAttributeMaxDynamicSharedMemorySize, SMEM_QF);
    cudaFuncSetAttribute(gram_kernel, cudaFuncAttributeMaxDynamicSharedMemorySize, SMEM_GRAM);

    dim3 tpb(256);
    proj_kernel<<<dim3(7, 16, Bn), tpb>>>(x, w1, b1, 0);
    proj_kernel<<<dim3(7, 16, Bn), tpb>>>(x, w2, b2, 1);
    gather_kernel<<<Bn * HS + Bn * On * HS, 160>>>();
    gram_kernel<<<dim3(On, Bn, 2), 288, SMEM_GRAM>>>();
    qform_kernel<<<dim3(8, On, Bn), 256, SMEM_QF>>>();
    big_mma<<<dim3(HS / 256, On, Bn), dim3(512), SMEM_MMA>>>(out);
}